// round 14
// baseline (speedup 1.0000x reference)
#include <cuda_runtime.h>
#include <math.h>

#define BB 8
#define NN 4096
#define NQ1 2048
#define NQ2 2048
#define KTOT 64
#define FINF 3.4e38f
#define FULLM 0xffffffffu
#define LOG2E 1.4426950408889634f

// Scratch (allocation-free rule: __device__ globals)
__device__ float4 g_feats[(long)BB * NN * KTOT];   // [pt][slot] = (rx,ry,rz,dist)
__device__ float4 g_qpos[(long)BB * NN];           // query position per point
__device__ float4 g_sdbs[3L * BB * NN];            // x-sorted dbs (w = 0.5|p|^2)
__device__ float4 g_qs[(long)BB * NN];             // x-sorted queries (w = idx bits)
__device__ float  g_G[16];                         // 0.125*log2e * Wq Wk^T
__device__ float  g_v[4];                          // 0.125*log2e * Wk bq

__device__ __forceinline__ float ex2f(float x) {
    float r;
    asm("ex2.approx.f32 %0, %1;" : "=f"(r) : "f"(x));
    return r;
}

__device__ __forceinline__ unsigned long long fkey(float x, int i) {
    unsigned u = __float_as_uint(x);
    u = (u & 0x80000000u) ? ~u : (u | 0x80000000u);
    return ((unsigned long long)u << 32) | (unsigned)i;
}

// ---------------------------------------------------------------------------
// In-smem bitonic sort of NN uint64 keys (512 threads).
// ---------------------------------------------------------------------------
__device__ __forceinline__ void block_sort(unsigned long long* sk) {
    for (int k = 2; k <= NN; k <<= 1) {
        for (int j = k >> 1; j > 0; j >>= 1) {
            for (int t = threadIdx.x; t < NN / 2; t += 512) {
                int i = 2 * t - (t & (j - 1));
                int l = i + j;
                bool asc = (i & k) == 0;
                unsigned long long a = sk[i], c = sk[l];
                if ((a > c) == asc) { sk[i] = c; sk[l] = a; }
            }
            __syncthreads();
        }
    }
}

// Sort each (batch, source) db by x; emit float4(x,y,z,0.5|p|^2) in x order.
__global__ __launch_bounds__(512) void sortdb_kernel(
    const float* __restrict__ p1, const float* __restrict__ p2,
    const float* __restrict__ pc) {
    __shared__ unsigned long long sk[NN];   // 32KB
    const int b = blockIdx.x, z = blockIdx.y;
    const float* src = ((z == 0) ? p1 : (z == 1) ? p2 : pc) + (long)b * 3 * NN;
    for (int i = threadIdx.x; i < NN; i += 512) sk[i] = fkey(src[i], i);
    __syncthreads();
    block_sort(sk);
    float4* dst = g_sdbs + ((long)z * BB + b) * NN;
    for (int r = threadIdx.x; r < NN; r += 512) {
        int i = (int)(sk[r] & 0xffffffffu);
        float x = src[i], y = src[NN + i], zz = src[2 * NN + i];
        dst[r] = make_float4(x, y, zz, 0.5f * fmaf(x, x, fmaf(y, y, zz * zz)));
    }
}

// Build + x-sort the fused query set per batch; block 0 also precomputes the
// scaled attention constants.
__global__ __launch_bounds__(512) void sortq_kernel(
    const float* __restrict__ p1, const float* __restrict__ p2,
    const int* __restrict__ ridx1, const int* __restrict__ ridx2,
    const float* __restrict__ Wq, const float* __restrict__ Wk,
    const float* __restrict__ bq) {
    __shared__ unsigned long long sk[NN];
    const int b = blockIdx.x;
    if (b == 0 && threadIdx.x < 20) {
        int t = threadIdx.x;
        float s = 0.f;
        if (t < 16) {
            int i = t >> 2, j = t & 3;
            for (int c = 0; c < 64; c++) s = fmaf(Wq[i * 64 + c], Wk[j * 64 + c], s);
            g_G[t] = 0.125f * LOG2E * s;
        } else {
            int j = t - 16;
            for (int c = 0; c < 64; c++) s = fmaf(Wk[j * 64 + c], bq[c], s);
            g_v[j] = 0.125f * LOG2E * s;
        }
    }
    const float* s1 = p1 + (long)b * 3 * NN;
    const float* s2 = p2 + (long)b * 3 * NN;
    for (int i = threadIdx.x; i < NN; i += 512) {
        float x = (i < NQ1) ? s1[ridx1[b * NQ1 + i]]
                            : s2[ridx2[b * NQ2 + (i - NQ1)]];
        sk[i] = fkey(x, i);
    }
    __syncthreads();
    block_sort(sk);
    for (int r = threadIdx.x; r < NN; r += 512) {
        int i = (int)(sk[r] & 0xffffffffu);
        int idx;
        const float* s;
        if (i < NQ1) { idx = ridx1[b * NQ1 + i]; s = s1; }
        else { idx = ridx2[b * NQ2 + (i - NQ1)]; s = s2; }
        g_qs[(long)b * NN + r] = make_float4(s[idx], s[NN + idx], s[2 * NN + idx],
                                             __uint_as_float((unsigned)i));
    }
}

// ---------------------------------------------------------------------------
// Warp sorting primitives (R11 verbatim).
// ---------------------------------------------------------------------------
__device__ __forceinline__ void cex_stage(float& s, int& i, int lane, int j,
                                          bool asc_block) {
    float os = __shfl_xor_sync(FULLM, s, j);
    int oi = __shfl_xor_sync(FULLM, i, j);
    bool lower = (lane & j) == 0;
    bool takeMin = (lower == asc_block);
    bool take = takeMin ? (os < s) : (os > s);
    if (take) { s = os; i = oi; }
}

__device__ __forceinline__ void sort32(float& s, int& i, int lane) {
#pragma unroll
    for (int k = 2; k <= 32; k <<= 1) {
#pragma unroll
        for (int j = k >> 1; j > 0; j >>= 1) {
            cex_stage(s, i, lane, j, (lane & k) == 0 || k == 32);
        }
    }
}

__device__ __forceinline__ void clean32(float& s, int& i, int lane) {
#pragma unroll
    for (int j = 16; j > 0; j >>= 1) cex_stage(s, i, lane, j, true);
}

__device__ __forceinline__ void knn_flush(uint2* buf, int lane, float& s0,
                                          int& i0, int& pend, float& thr,
                                          int K) {
    __syncwarp();
    float s1 = FINF;
    int i1 = 0;
    if (lane < pend) {
        uint2 e = buf[lane];
        s1 = __uint_as_float(e.x);
        i1 = (int)e.y;
    }
    sort32(s1, i1, lane);
    float os = __shfl_sync(FULLM, s1, 31 - lane);
    int oi = __shfl_sync(FULLM, i1, 31 - lane);
    if (os < s0) { s0 = os; i0 = oi; }
    clean32(s0, i0, lane);
    thr = __shfl_sync(FULLM, s0, K - 1);
    pend = 0;
}

// One 32-point batch: R11 scan body with an in-range mask (for array edges).
__device__ __forceinline__ void scan_batch32(
    const float4* __restrict__ sdb, uint2 (*scand)[32], int lane, unsigned lt,
    int base, int K,
    const float (&qnx)[4], const float (&qny)[4], const float (&qnz)[4],
    float (&s0)[4], float (&thr)[4], int (&i0)[4], int (&pend)[4]) {
    int idx = base + lane;
    bool inr = (unsigned)idx < (unsigned)NN;
    float4 p = sdb[inr ? idx : 0];
    float sc[4];
#pragma unroll
    for (int q = 0; q < 4; q++)
        sc[q] = fmaf(qnx[q], p.x, fmaf(qny[q], p.y, fmaf(qnz[q], p.z, p.w)));
#pragma unroll
    for (int q = 0; q < 4; q++) {
        unsigned m = __ballot_sync(FULLM, inr && (sc[q] < thr[q]));
        if (m) {                               // warp-uniform
            int n = __popc(m);
            if (pend[q] + n > 32) {
                knn_flush(scand[q], lane, s0[q], i0[q], pend[q], thr[q], K);
                m = __ballot_sync(FULLM, inr && (sc[q] < thr[q]));
                n = __popc(m);
            }
            if (inr && (sc[q] < thr[q])) {
                scand[q][pend[q] + __popc(m & lt)] =
                    make_uint2(__float_as_uint(sc[q]), (unsigned)idx);
            }
            pend[q] += n;
        }
    }
}

// ---------------------------------------------------------------------------
// Windowed brute-force KNN over x-sorted db. grid.z selects (db, K, slot).
// Exact: stop edges use d^2 >= (x-distance)^2 with the current threshold.
// ---------------------------------------------------------------------------
__global__ __launch_bounds__(512, 2) void knn_kernel() {
    extern __shared__ float4 sdb[];        // NN entries, 64KB
    __shared__ uint2 scand[16][4][32];

    const int z = blockIdx.z;
    const int b = blockIdx.y;
    const int K = (z == 2) ? 32 : 16;
    const int slot_base = z * 16;

    const float4* gsd = g_sdbs + ((long)z * BB + b) * NN;
    for (int j = threadIdx.x; j < NN; j += 512) sdb[j] = gsd[j];
    __syncthreads();

    const int w = threadIdx.x >> 5;
    const int lane = threadIdx.x & 31;
    const int qslot = blockIdx.x * 64 + w * 4;   // 4 x-adjacent sorted queries
    const unsigned lt = (1u << lane) - 1u;

    float qnx[4], qny[4], qnz[4], qn2[4];
#pragma unroll
    for (int q = 0; q < 4; q++) {
        float4 qv = g_qs[(long)b * NN + qslot + q];
        qnx[q] = -qv.x; qny[q] = -qv.y; qnz[q] = -qv.z;
        qn2[q] = fmaf(qv.x, qv.x, fmaf(qv.y, qv.y, qv.z * qv.z));
    }

    // Binary search: first sorted-db index with x >= qx(query 0).
    float target = -qnx[0];
    int lo = 0, hi = NN;
#pragma unroll
    for (int it = 0; it < 12; it++) {
        int mid = (lo + hi) >> 1;
        bool lt2 = sdb[mid].x < target;
        lo = lt2 ? mid + 1 : lo;
        hi = lt2 ? hi : mid;
    }
    const int s = min(max(lo - 32, 0), NN - 64);

    // Seed: exact sorted bottom-32 of the 64 x-nearest points.
    float s0[4], thr[4];
    int i0[4], pend[4];
    {
        float4 pa = sdb[s + lane];
        float4 pb = sdb[s + 32 + lane];
#pragma unroll
        for (int q = 0; q < 4; q++) {
            float sa = fmaf(qnx[q], pa.x, fmaf(qny[q], pa.y, fmaf(qnz[q], pa.z, pa.w)));
            int ia = s + lane;
            sort32(sa, ia, lane);
            float sb = fmaf(qnx[q], pb.x, fmaf(qny[q], pb.y, fmaf(qnz[q], pb.z, pb.w)));
            int ib = s + 32 + lane;
            sort32(sb, ib, lane);
            float os = __shfl_sync(FULLM, sb, 31 - lane);
            int oi = __shfl_sync(FULLM, ib, 31 - lane);
            if (os < sa) { sa = os; ia = oi; }
            clean32(sa, ia, lane);
            s0[q] = sa; i0[q] = ia;
            thr[q] = __shfl_sync(FULLM, sa, K - 1);
            pend[q] = 0;
        }
    }

    // Alternating outward walk in 64-point super-batches with exact stops.
    int R = s + 64, L = s;
    bool goR = true, goL = true;
    while (goR || goL) {
        if (goR) {
            if (R >= NN) {
                goR = false;
            } else {
                float ex = sdb[R].x;
                bool need = false;
#pragma unroll
                for (int q = 0; q < 4; q++) {
                    float dx = ex + qnx[q];            // = x_edge - qx
                    need |= !((dx > 0.f) &&
                              (dx * dx > fmaf(2.f, thr[q], qn2[q])));
                }
                if (!need) {
                    goR = false;
                } else {
                    scan_batch32(sdb, scand[w], lane, lt, R, K,
                                 qnx, qny, qnz, s0, thr, i0, pend);
                    scan_batch32(sdb, scand[w], lane, lt, R + 32, K,
                                 qnx, qny, qnz, s0, thr, i0, pend);
                    R += 64;
                }
            }
        }
        if (goL) {
            if (L <= 0) {
                goL = false;
            } else {
                float ex = sdb[L - 1].x;
                bool need = false;
#pragma unroll
                for (int q = 0; q < 4; q++) {
                    float dx = -(ex + qnx[q]);         // = qx - x_edge
                    need |= !((dx > 0.f) &&
                              (dx * dx > fmaf(2.f, thr[q], qn2[q])));
                }
                if (!need) {
                    goL = false;
                } else {
                    scan_batch32(sdb, scand[w], lane, lt, L - 64, K,
                                 qnx, qny, qnz, s0, thr, i0, pend);
                    scan_batch32(sdb, scand[w], lane, lt, L - 32, K,
                                 qnx, qny, qnz, s0, thr, i0, pend);
                    L -= 64;
                }
            }
        }
    }

#pragma unroll
    for (int q = 0; q < 4; q++) {
        if (pend[q])
            knn_flush(scand[w][q], lane, s0[q], i0[q], pend[q], thr[q], K);
        int orig = (int)__float_as_uint(g_qs[(long)b * NN + qslot + q].w);
        const long pt = (long)b * NN + orig;
        if (lane < K) {
            float4 p = sdb[i0[q]];
            float rx = p.x + qnx[q], ry = p.y + qny[q], rz = p.z + qnz[q];
            float sq = fmaf(rx, rx, fmaf(ry, ry, rz * rz));
            float dd = (sq > 0.f) ? sqrtf(sq) : 0.f;
            g_feats[pt * KTOT + slot_base + lane] = make_float4(rx, ry, rz, dd);
        }
        if (z == 0 && lane == 0) {
            g_qpos[pt] = make_float4(-qnx[q], -qny[q], -qnz[q], 0.f);
        }
    }
}

// ---------------------------------------------------------------------------
// Attention + weighted fusion (R11 verbatim).
// ---------------------------------------------------------------------------
__global__ __launch_bounds__(256) void attn_kernel(float* __restrict__ out,
                                                   const float* __restrict__ Wv,
                                                   const float* __restrict__ bv) {
    __shared__ float4 sF[4][64];
    __shared__ float  sB[4][64];
    __shared__ float4 sWv4[64];
    __shared__ float  sbv[64];
    __shared__ float  sSum[4][2];
    __shared__ float  sRed[4][2][3];

    const int tid = threadIdx.x;
    const int g = tid >> 6;
    const int t = tid & 63;

    if (tid < 64) {
        sWv4[tid] = make_float4(LOG2E * Wv[tid], LOG2E * Wv[64 + tid],
                                LOG2E * Wv[128 + tid], LOG2E * Wv[192 + tid]);
        sbv[tid] = LOG2E * bv[tid];
    }

    const long pt = (long)blockIdx.x * 4 + g;

    float4 F = g_feats[pt * KTOT + t];
    sF[g][t] = F;

    float P0 = F.x * g_G[0]  + F.y * g_G[4]  + F.z * g_G[8]  + F.w * g_G[12];
    float P1 = F.x * g_G[1]  + F.y * g_G[5]  + F.z * g_G[9]  + F.w * g_G[13];
    float P2 = F.x * g_G[2]  + F.y * g_G[6]  + F.z * g_G[10] + F.w * g_G[14];
    float P3 = F.x * g_G[3]  + F.y * g_G[7]  + F.z * g_G[11] + F.w * g_G[15];
    sB[g][t] = F.x * g_v[0] + F.y * g_v[1] + F.z * g_v[2] + F.w * g_v[3];

    __syncthreads();

    float ssum = 0.f, a0 = 0.f, a1 = 0.f, a2 = 0.f, a3 = 0.f;
#pragma unroll 8
    for (int j = 0; j < 64; j++) {
        float4 Fj = sF[g][j];
        float l = fmaf(P0, Fj.x, fmaf(P1, Fj.y, fmaf(P2, Fj.z, fmaf(P3, Fj.w, sB[g][j]))));
        float e = ex2f(l);
        ssum += e;
        a0 = fmaf(e, Fj.x, a0);
        a1 = fmaf(e, Fj.y, a1);
        a2 = fmaf(e, Fj.z, a2);
        a3 = fmaf(e, Fj.w, a3);
    }
    float inv = 1.f / ssum;
    a0 *= inv; a1 *= inv; a2 *= inv; a3 *= inv;

    float sc = -FINF;
#pragma unroll 8
    for (int c = 0; c < 64; c++) {
        float4 wv = sWv4[c];
        float y = fmaf(a0, wv.x, fmaf(a1, wv.y, fmaf(a2, wv.z, fmaf(a3, wv.w, sbv[c]))));
        sc = fmaxf(sc, y);
    }

    float e_t = ex2f(sc);
    float ws = e_t;
#pragma unroll
    for (int off = 16; off > 0; off >>= 1)
        ws += __shfl_xor_sync(FULLM, ws, off);
    const int wg = t >> 5;
    if ((t & 31) == 0) sSum[g][wg] = ws;
    __syncthreads();
    float wgt = e_t / (sSum[g][0] + sSum[g][1]);

    float cx = wgt * F.x, cy = wgt * F.y, cz = wgt * F.z;
#pragma unroll
    for (int off = 16; off > 0; off >>= 1) {
        cx += __shfl_down_sync(FULLM, cx, off);
        cy += __shfl_down_sync(FULLM, cy, off);
        cz += __shfl_down_sync(FULLM, cz, off);
    }
    if ((t & 31) == 0) {
        sRed[g][wg][0] = cx; sRed[g][wg][1] = cy; sRed[g][wg][2] = cz;
    }
    __syncthreads();
    if (t == 0) {
        int b = (int)(pt / NN);
        int n = (int)(pt % NN);
        float4 qp = g_qpos[pt];
        out[(long)b * 3 * NN + 0 * NN + n] = sRed[g][0][0] + sRed[g][1][0] + qp.x;
        out[(long)b * 3 * NN + 1 * NN + n] = sRed[g][0][1] + sRed[g][1][1] + qp.y;
        out[(long)b * 3 * NN + 2 * NN + n] = sRed[g][0][2] + sRed[g][1][2] + qp.z;
    }
}

// ---------------------------------------------------------------------------
extern "C" void kernel_launch(void* const* d_in, const int* in_sizes, int n_in,
                              void* d_out, int out_size) {
    const float* points1 = (const float*)d_in[0];
    const float* points2 = (const float*)d_in[1];
    const float* pc      = (const float*)d_in[2];
    const float* Wq      = (const float*)d_in[3];
    const float* Wk      = (const float*)d_in[4];
    const float* Wv      = (const float*)d_in[5];
    const float* bq      = (const float*)d_in[6];
    const float* bv      = (const float*)d_in[8];
    const int*   ridx1   = (const int*)d_in[9];
    const int*   ridx2   = (const int*)d_in[10];
    float* out = (float*)d_out;

    const size_t smem = (size_t)NN * sizeof(float4);  // 64KB dynamic
    cudaFuncSetAttribute(knn_kernel, cudaFuncAttributeMaxDynamicSharedMemorySize, (int)smem);

    sortdb_kernel<<<dim3(BB, 3), 512>>>(points1, points2, pc);
    sortq_kernel<<<BB, 512>>>(points1, points2, ridx1, ridx2, Wq, Wk, bq);

    dim3 grid(NN / 64, BB, 3);
    knn_kernel<<<grid, 512, smem>>>();

    attn_kernel<<<(BB * NN) / 4, 256>>>(out, Wv, bv);
}

// round 15
// speedup vs baseline: 2.1718x; 2.1718x over previous
#include <cuda_runtime.h>
#include <math.h>

#define BB 8
#define NN 4096
#define NQ1 2048
#define NQ2 2048
#define KTOT 64
#define FINF 3.4e38f
#define FULLM 0xffffffffu
#define LOG2E 1.4426950408889634f

// Scratch (allocation-free rule: __device__ globals)
__device__ float4 g_feats[(long)BB * NN * KTOT];   // [pt][slot] = (rx,ry,rz,dist)
__device__ float4 g_qpos[(long)BB * NN];           // query position per point
__device__ float  g_G[16];                         // 0.125*log2e * Wq Wk^T
__device__ float  g_v[4];                          // 0.125*log2e * Wk bq

__device__ __forceinline__ float ex2f(float x) {
    float r;
    asm("ex2.approx.f32 %0, %1;" : "=f"(r) : "f"(x));
    return r;
}

// ---------------------------------------------------------------------------
// Warp sorting primitives: one (score,idx) element per lane.
// ---------------------------------------------------------------------------
__device__ __forceinline__ void cex_stage(float& s, int& i, int lane, int j,
                                          bool asc_block) {
    float os = __shfl_xor_sync(FULLM, s, j);
    int oi = __shfl_xor_sync(FULLM, i, j);
    bool lower = (lane & j) == 0;
    bool takeMin = (lower == asc_block);
    bool take = takeMin ? (os < s) : (os > s);
    if (take) { s = os; i = oi; }
}

__device__ __forceinline__ void sort32(float& s, int& i, int lane) {
#pragma unroll
    for (int k = 2; k <= 32; k <<= 1) {
#pragma unroll
        for (int j = k >> 1; j > 0; j >>= 1) {
            cex_stage(s, i, lane, j, (lane & k) == 0 || k == 32);
        }
    }
}

__device__ __forceinline__ void clean32(float& s, int& i, int lane) {
#pragma unroll
    for (int j = 16; j > 0; j >>= 1) cex_stage(s, i, lane, j, true);
}

// Flush: merge sorted kept list (s0,i0 ascending over lanes; exact top-32 so
// far) with `pend` unsorted candidates in buf[0..pend). Result: s0 = smallest
// 32 of the union, sorted ascending; thr = K-th smallest; pend = 0.
__device__ __forceinline__ void knn_flush(uint2* buf, int lane, float& s0,
                                          int& i0, int& pend, float& thr,
                                          int K) {
    __syncwarp();
    float s1 = FINF;
    int i1 = 0;
    if (lane < pend) {
        uint2 e = buf[lane];
        s1 = __uint_as_float(e.x);
        i1 = (int)e.y;
    }
    sort32(s1, i1, lane);
    // bitonic merge lower half: L[i] = min(kept[i], cand[31-i])
    float os = __shfl_sync(FULLM, s1, 31 - lane);
    int oi = __shfl_sync(FULLM, i1, 31 - lane);
    if (os < s0) { s0 = os; i0 = oi; }
    clean32(s0, i0, lane);
    thr = __shfl_sync(FULLM, s0, K - 1);
    pend = 0;
}

// ---------------------------------------------------------------------------
// Fused brute-force KNN: grid.z selects (db, K, slot). 4 queries per warp;
// smem pending buffer + bitonic flush (measured-best loop). One block also
// computes the scaled rank-4 attention constants.
// ---------------------------------------------------------------------------
__global__ __launch_bounds__(512, 2) void knn_kernel(
    const float* __restrict__ p1, const float* __restrict__ p2,
    const float* __restrict__ pc,
    const int* __restrict__ ridx1, const int* __restrict__ ridx2,
    const float* __restrict__ Wq, const float* __restrict__ Wk,
    const float* __restrict__ bq) {
    extern __shared__ float4 sdb[];        // NN entries, 64KB (w = 0.5*|p|^2)
    __shared__ uint2 scand[16][4][32];     // per-warp, per-query pending buf

    const int z = blockIdx.z;
    const int b = blockIdx.y;
    const int K = (z == 2) ? 32 : 16;
    const int slot_base = z * 16;          // 0, 16, 32
    const float* db = (z == 0) ? p1 : (z == 1) ? p2 : pc;

    // Inline precompute (one block): G = 0.125*log2e*Wq Wk^T, v likewise.
    if (z == 2 && blockIdx.x == 0 && b == 0 && threadIdx.x < 20) {
        int t = threadIdx.x;
        float s = 0.f;
        if (t < 16) {
            int i = t >> 2, j = t & 3;
            for (int c = 0; c < 64; c++) s = fmaf(Wq[i * 64 + c], Wk[j * 64 + c], s);
            g_G[t] = 0.125f * LOG2E * s;
        } else {
            int j = t - 16;
            for (int c = 0; c < 64; c++) s = fmaf(Wk[j * 64 + c], bq[c], s);
            g_v[j] = 0.125f * LOG2E * s;
        }
    }

    const float* dbx = db + (long)b * 3 * NN;
    for (int j = threadIdx.x; j < NN; j += 512) {
        float x = dbx[j], y = dbx[NN + j], z2 = dbx[2 * NN + j];
        sdb[j] = make_float4(x, y, z2, 0.5f * fmaf(x, x, fmaf(y, y, z2 * z2)));
    }
    __syncthreads();

    const int w = threadIdx.x >> 5;
    const int lane = threadIdx.x & 31;
    const int qbase = blockIdx.x * 64 + w * 4;   // 4 consecutive queries/warp
    const unsigned lt = (1u << lane) - 1u;

    float qx[4], qy[4], qz[4];
#pragma unroll
    for (int q = 0; q < 4; q++) {
        int qi = qbase + q;
        if (qi < NQ1) {
            int idx = ridx1[b * NQ1 + qi];
            const float* s = p1 + (long)b * 3 * NN;
            qx[q] = -s[idx]; qy[q] = -s[NN + idx]; qz[q] = -s[2 * NN + idx];
        } else {
            int idx = ridx2[b * NQ2 + (qi - NQ1)];
            const float* s = p2 + (long)b * 3 * NN;
            qx[q] = -s[idx]; qy[q] = -s[NN + idx]; qz[q] = -s[2 * NN + idx];
        }
    }

    float s0[4], thr[4];
    int i0[4], pend[4];
    // Seed: per query, exact top-32 of batch 0 sorted across lanes.
    {
        float4 p = sdb[lane];
#pragma unroll
        for (int q = 0; q < 4; q++) {
            float s = fmaf(qx[q], p.x, fmaf(qy[q], p.y, fmaf(qz[q], p.z, p.w)));
            int i = lane;
            sort32(s, i, lane);
            s0[q] = s; i0[q] = i;
            thr[q] = __shfl_sync(FULLM, s, K - 1);
            pend[q] = 0;
        }
    }

    for (int j0 = 32; j0 < NN; j0 += 32) {
        float4 p = sdb[j0 + lane];
        float sc[4];
#pragma unroll
        for (int q = 0; q < 4; q++)
            sc[q] = fmaf(qx[q], p.x, fmaf(qy[q], p.y, fmaf(qz[q], p.z, p.w)));
#pragma unroll
        for (int q = 0; q < 4; q++) {
            unsigned m = __ballot_sync(FULLM, sc[q] < thr[q]);
            if (m) {                               // warp-uniform
                int n = __popc(m);
                if (pend[q] + n > 32) {
                    knn_flush(scand[w][q], lane, s0[q], i0[q], pend[q],
                              thr[q], K);
                    m = __ballot_sync(FULLM, sc[q] < thr[q]);
                    n = __popc(m);
                }
                if (sc[q] < thr[q]) {
                    scand[w][q][pend[q] + __popc(m & lt)] =
                        make_uint2(__float_as_uint(sc[q]),
                                   (unsigned)(j0 + lane));
                }
                pend[q] += n;
            }
        }
    }

#pragma unroll
    for (int q = 0; q < 4; q++) {
        if (pend[q])
            knn_flush(scand[w][q], lane, s0[q], i0[q], pend[q], thr[q], K);
        const long pt = (long)b * NN + qbase + q;
        if (lane < K) {
            float4 p = sdb[i0[q]];
            float rx = p.x + qx[q], ry = p.y + qy[q], rz = p.z + qz[q];
            float sq = fmaf(rx, rx, fmaf(ry, ry, rz * rz));
            float dd = (sq > 0.f) ? sqrtf(sq) : 0.f;
            g_feats[pt * KTOT + slot_base + lane] = make_float4(rx, ry, rz, dd);
        }
        if (z == 0 && lane == 0) {
            g_qpos[pt] = make_float4(-qx[q], -qy[q], -qz[q], 0.f);
        }
    }
}

// ---------------------------------------------------------------------------
// Attention + weighted fusion. Rank-4 factorization; per-row term dropped
// (cancels in softmax); 0.125 and log2e folded into constants so both
// softmax exps are raw ex2.approx.
// ---------------------------------------------------------------------------
__global__ __launch_bounds__(256) void attn_kernel(float* __restrict__ out,
                                                   const float* __restrict__ Wv,
                                                   const float* __restrict__ bv) {
    __shared__ float4 sF[4][64];
    __shared__ float  sB[4][64];     // scaled F_j . v column terms
    __shared__ float4 sWv4[64];      // log2e * (Wv[0..3][c])
    __shared__ float  sbv[64];       // log2e * bv
    __shared__ float  sSum[4][2];
    __shared__ float  sRed[4][2][3];

    const int tid = threadIdx.x;
    const int g = tid >> 6;
    const int t = tid & 63;

    if (tid < 64) {
        sWv4[tid] = make_float4(LOG2E * Wv[tid], LOG2E * Wv[64 + tid],
                                LOG2E * Wv[128 + tid], LOG2E * Wv[192 + tid]);
        sbv[tid] = LOG2E * bv[tid];
    }

    const long pt = (long)blockIdx.x * 4 + g;

    float4 F = g_feats[pt * KTOT + t];
    sF[g][t] = F;

    float P0 = F.x * g_G[0]  + F.y * g_G[4]  + F.z * g_G[8]  + F.w * g_G[12];
    float P1 = F.x * g_G[1]  + F.y * g_G[5]  + F.z * g_G[9]  + F.w * g_G[13];
    float P2 = F.x * g_G[2]  + F.y * g_G[6]  + F.z * g_G[10] + F.w * g_G[14];
    float P3 = F.x * g_G[3]  + F.y * g_G[7]  + F.z * g_G[11] + F.w * g_G[15];
    sB[g][t] = F.x * g_v[0] + F.y * g_v[1] + F.z * g_v[2] + F.w * g_v[3];

    __syncthreads();

    // Single pass: softmax (base-2 domain, exactly e^logit) fused with attn@F.
    float ssum = 0.f, a0 = 0.f, a1 = 0.f, a2 = 0.f, a3 = 0.f;
#pragma unroll 8
    for (int j = 0; j < 64; j++) {
        float4 Fj = sF[g][j];
        float l = fmaf(P0, Fj.x, fmaf(P1, Fj.y, fmaf(P2, Fj.z, fmaf(P3, Fj.w, sB[g][j]))));
        float e = ex2f(l);
        ssum += e;
        a0 = fmaf(e, Fj.x, a0);
        a1 = fmaf(e, Fj.y, a1);
        a2 = fmaf(e, Fj.z, a2);
        a3 = fmaf(e, Fj.w, a3);
    }
    float inv = 1.f / ssum;
    a0 *= inv; a1 *= inv; a2 *= inv; a3 *= inv;

    // score (log2e-scaled) = max over 64 channels of AF . Wv'[:,c] + bv'[c]
    float sc = -FINF;
#pragma unroll 8
    for (int c = 0; c < 64; c++) {
        float4 wv = sWv4[c];
        float y = fmaf(a0, wv.x, fmaf(a1, wv.y, fmaf(a2, wv.z, fmaf(a3, wv.w, sbv[c]))));
        sc = fmaxf(sc, y);
    }

    // softmax over the 64 neighbors; 2^(log2e*s) = e^s.
    float e_t = ex2f(sc);
    float ws = e_t;
#pragma unroll
    for (int off = 16; off > 0; off >>= 1)
        ws += __shfl_xor_sync(FULLM, ws, off);
    const int wg = t >> 5;
    if ((t & 31) == 0) sSum[g][wg] = ws;
    __syncthreads();
    float wgt = e_t / (sSum[g][0] + sSum[g][1]);

    // weighted sum of resi across 64 threads (grouped = resi + qpos).
    float cx = wgt * F.x, cy = wgt * F.y, cz = wgt * F.z;
#pragma unroll
    for (int off = 16; off > 0; off >>= 1) {
        cx += __shfl_down_sync(FULLM, cx, off);
        cy += __shfl_down_sync(FULLM, cy, off);
        cz += __shfl_down_sync(FULLM, cz, off);
    }
    if ((t & 31) == 0) {
        sRed[g][wg][0] = cx; sRed[g][wg][1] = cy; sRed[g][wg][2] = cz;
    }
    __syncthreads();
    if (t == 0) {
        int b = (int)(pt / NN);
        int n = (int)(pt % NN);
        float4 qp = g_qpos[pt];
        out[(long)b * 3 * NN + 0 * NN + n] = sRed[g][0][0] + sRed[g][1][0] + qp.x;
        out[(long)b * 3 * NN + 1 * NN + n] = sRed[g][0][1] + sRed[g][1][1] + qp.y;
        out[(long)b * 3 * NN + 2 * NN + n] = sRed[g][0][2] + sRed[g][1][2] + qp.z;
    }
}

// ---------------------------------------------------------------------------
extern "C" void kernel_launch(void* const* d_in, const int* in_sizes, int n_in,
                              void* d_out, int out_size) {
    const float* points1 = (const float*)d_in[0];
    const float* points2 = (const float*)d_in[1];
    const float* pc      = (const float*)d_in[2];
    const float* Wq      = (const float*)d_in[3];
    const float* Wk      = (const float*)d_in[4];
    const float* Wv      = (const float*)d_in[5];
    const float* bq      = (const float*)d_in[6];
    const float* bv      = (const float*)d_in[8];
    const int*   ridx1   = (const int*)d_in[9];
    const int*   ridx2   = (const int*)d_in[10];
    float* out = (float*)d_out;

    const size_t smem = (size_t)NN * sizeof(float4);  // 64KB dynamic
    cudaFuncSetAttribute(knn_kernel, cudaFuncAttributeMaxDynamicSharedMemorySize, (int)smem);

    // 64 query-chunks (64 queries each) x 8 batches x 3 knn types
    dim3 grid(NN / 64, BB, 3);
    knn_kernel<<<grid, 512, smem>>>(points1, points2, pc, ridx1, ridx2,
                                    Wq, Wk, bq);

    attn_kernel<<<(BB * NN) / 4, 256>>>(out, Wv, bv);
}